// round 16
// baseline (speedup 1.0000x reference)
#include <cuda_runtime.h>
#include <cuda_bf16.h>
#include <cstdint>

#define D_MODEL 1024
#define KV_DIM 256
#define N_HEADS 16
#define HEAD_DIM 64
#define TSEQ 2048
#define BATCH 2
#define BT (BATCH * TSEQ)
#define KH2 (D_MODEL / 2)
#define QSCALE (0.125f * 1.4426950408889634f)   // 1/sqrt(64) * log2(e)
#define N_JOBS (16 * N_HEADS * BATCH)           // 512 attention tile-jobs
#define PLANE (TSEQ * HEAD_DIM)                 // 131072 floats per (b,g)

// Scratch (device globals; no allocation anywhere).
__device__ float g_Q[(size_t)BT * D_MODEL];
// K quad-interleaved: plane(b,g) -> [t][pos(d)], pos = (d>>4)*16+(d&3)*4+((d>>2)&3)
__device__ float g_Kp[(size_t)BT * KV_DIM];
// V t-quad-interleaved (tf32): plane(b,g) ->
//   [blk=t>>4][d][(t&3)*4 + ((t>>2)&3)]   (blk stride 1024, d stride 16)
__device__ float g_Vp[(size_t)BT * KV_DIM];
__device__ int g_jobctr;
// packed bf16x2 hi/lo operands
__device__ uint32_t g_xh[(size_t)BT * KH2];
__device__ uint32_t g_xl[(size_t)BT * KH2];
__device__ uint32_t g_Oh[(size_t)BT * KH2];
__device__ uint32_t g_Ol[(size_t)BT * KH2];
__device__ uint32_t g_WqTh[(size_t)D_MODEL * KH2];
__device__ uint32_t g_WqTl[(size_t)D_MODEL * KH2];
__device__ uint32_t g_WkTh[(size_t)KV_DIM * KH2];
__device__ uint32_t g_WkTl[(size_t)KV_DIM * KH2];
__device__ uint32_t g_WvTh[(size_t)KV_DIM * KH2];
__device__ uint32_t g_WvTl[(size_t)KV_DIM * KH2];
__device__ uint32_t g_WoTh[(size_t)D_MODEL * KH2];
__device__ uint32_t g_WoTl[(size_t)D_MODEL * KH2];

// ---------------------------------------------------------------------------
// Helpers
// ---------------------------------------------------------------------------
__device__ __forceinline__ float f2tf32(float v) {
    uint32_t u; asm("cvt.rna.tf32.f32 %0, %1;" : "=r"(u) : "f"(v));
    return __uint_as_float(u);
}

__device__ __forceinline__ void mma1688(float* d, float a0, float a1, float a2,
                                        float a3, float b0, float b1) {
    asm volatile(
        "mma.sync.aligned.m16n8k8.row.col.f32.tf32.tf32.f32 "
        "{%0,%1,%2,%3}, {%4,%5,%6,%7}, {%8,%9}, {%0,%1,%2,%3};"
        : "+f"(d[0]), "+f"(d[1]), "+f"(d[2]), "+f"(d[3])
        : "r"(__float_as_uint(a0)), "r"(__float_as_uint(a1)),
          "r"(__float_as_uint(a2)), "r"(__float_as_uint(a3)),
          "r"(__float_as_uint(b0)), "r"(__float_as_uint(b1)));
}

__device__ __forceinline__ void mma16816(float* d, uint32_t a0, uint32_t a1,
                                         uint32_t a2, uint32_t a3,
                                         uint32_t b0, uint32_t b1) {
    asm volatile(
        "mma.sync.aligned.m16n8k16.row.col.f32.bf16.bf16.f32 "
        "{%0,%1,%2,%3}, {%4,%5,%6,%7}, {%8,%9}, {%0,%1,%2,%3};"
        : "+f"(d[0]), "+f"(d[1]), "+f"(d[2]), "+f"(d[3])
        : "r"(a0), "r"(a1), "r"(a2), "r"(a3), "r"(b0), "r"(b1));
}

__device__ __forceinline__ void ldsm4(uint32_t& r0, uint32_t& r1,
                                      uint32_t& r2, uint32_t& r3, uint32_t a) {
    asm volatile("ldmatrix.sync.aligned.m8n8.x4.shared.b16 {%0,%1,%2,%3}, [%4];"
                 : "=r"(r0), "=r"(r1), "=r"(r2), "=r"(r3) : "r"(a));
}

__device__ __forceinline__ uint32_t packbf(__nv_bfloat16 a, __nv_bfloat16 b) {
    __nv_bfloat162 t(a, b);
    return *reinterpret_cast<uint32_t*>(&t);
}

__device__ __forceinline__ uint32_t smem_u32p(const void* p) {
    uint32_t r;
    asm("{ .reg .u64 t; cvta.to.shared.u64 t, %1; cvt.u32.u64 %0, t; }"
        : "=r"(r) : "l"(p));
    return r;
}

__device__ __forceinline__ void cp16(uint32_t dst, const void* src) {
    asm volatile("cp.async.cg.shared.global [%0], [%1], 16;"
                 :: "r"(dst), "l"(src));
}
#define CP_COMMIT() asm volatile("cp.async.commit_group;" ::: "memory")
#define CP_WAIT0()  asm volatile("cp.async.wait_group 0;" ::: "memory")
#define CP_WAIT1()  asm volatile("cp.async.wait_group 1;" ::: "memory")

// K address: quad interleave within 64-float row.
__device__ __forceinline__ size_t kaddr(int m, int n) {
    const int t = m & (TSEQ - 1), d = n & 63;
    const size_t pl = (size_t)(((m >> 11) << 2) + (n >> 6)) * PLANE;
    const int pos = ((d >> 4) << 4) + ((d & 3) << 2) + ((d >> 2) & 3);
    return pl + (size_t)t * 64 + pos;
}
// V address: t-quad interleave (tf32 floats).
__device__ __forceinline__ size_t vaddr(int m, int n) {
    const int t = m & (TSEQ - 1), d = n & 63;
    const size_t pl = (size_t)(((m >> 11) << 2) + (n >> 6)) * PLANE;
    return pl + (size_t)(t >> 4) * 1024 + d * 16 + ((t & 3) << 2) + ((t >> 2) & 3);
}

// ---------------------------------------------------------------------------
// One-shot converters
// ---------------------------------------------------------------------------
__global__ __launch_bounds__(256) void conv_pack(
    const float* __restrict__ A, uint32_t* __restrict__ H,
    uint32_t* __restrict__ L, int n4)
{
    int i = blockIdx.x * blockDim.x + threadIdx.x;
    if (i == 0) g_jobctr = 0;
    if (i >= n4) return;
    float4 v = ((const float4*)A)[i];
    __nv_bfloat16 hx = __float2bfloat16_rn(v.x);
    __nv_bfloat16 hy = __float2bfloat16_rn(v.y);
    __nv_bfloat16 hz = __float2bfloat16_rn(v.z);
    __nv_bfloat16 hw = __float2bfloat16_rn(v.w);
    ((uint2*)H)[i] = make_uint2(packbf(hx, hy), packbf(hz, hw));
    ((uint2*)L)[i] = make_uint2(
        packbf(__float2bfloat16_rn(v.x - __bfloat162float(hx)),
               __float2bfloat16_rn(v.y - __bfloat162float(hy))),
        packbf(__float2bfloat16_rn(v.z - __bfloat162float(hz)),
               __float2bfloat16_rn(v.w - __bfloat162float(hw))));
}

__global__ __launch_bounds__(256) void conv_wT_all(
    const float* __restrict__ Wq, const float* __restrict__ Wk,
    const float* __restrict__ Wv, const float* __restrict__ Wo)
{
    const float* W; uint32_t* H; uint32_t* L; int N;
    switch (blockIdx.z) {
        case 0: W = Wq; H = g_WqTh; L = g_WqTl; N = D_MODEL; break;
        case 1: W = Wk; H = g_WkTh; L = g_WkTl; N = KV_DIM;  break;
        case 2: W = Wv; H = g_WvTh; L = g_WvTl; N = KV_DIM;  break;
        default:W = Wo; H = g_WoTh; L = g_WoTl; N = D_MODEL; break;
    }
    const int n0 = blockIdx.x * 32, k0 = blockIdx.y * 32;
    if (n0 >= N) return;
    __shared__ float t[32][33];
    const int tx = threadIdx.x, ty = threadIdx.y;
#pragma unroll
    for (int i = 0; i < 4; i++)
        t[ty + i * 8][tx] = W[(size_t)(k0 + ty + i * 8) * N + n0 + tx];
    __syncthreads();
#pragma unroll
    for (int i = 0; i < 2; i++) {
        const int kp = ty + i * 8;
        float a = t[kp * 2][tx], b = t[kp * 2 + 1][tx];
        __nv_bfloat16 ha = __float2bfloat16_rn(a);
        __nv_bfloat16 hb = __float2bfloat16_rn(b);
        const size_t o = (size_t)(n0 + tx) * KH2 + k0 / 2 + kp;
        H[o] = packbf(ha, hb);
        L[o] = packbf(__float2bfloat16_rn(a - __bfloat162float(ha)),
                      __float2bfloat16_rn(b - __bfloat162float(hb)));
    }
}

// ---------------------------------------------------------------------------
// 2-term bf16-split GEMM, cp.async double-buffered, ldmatrix fragment loads.
// MODE: 0 = plain fp32; 1 = tf32(premul) row-major (Q);
//       2 = tf32 K quad-interleave; 3 = tf32 V t-quad-interleave.
// ---------------------------------------------------------------------------
#define GROW 20
#define G_AH 0
#define G_AL (128 * GROW)
#define G_BH (2 * 128 * GROW)
#define G_BL (3 * 128 * GROW)
#define G_U32 (4 * 128 * GROW)
#define GEMM_SMEM (2 * G_U32 * 4)

__device__ __forceinline__ void gemm_stage(
    uint32_t sbase, const uint32_t* __restrict__ AH,
    const uint32_t* __restrict__ AL, const uint32_t* __restrict__ BH,
    const uint32_t* __restrict__ BL, int KH, int m0, int n0, int kc2)
{
    const int tid = threadIdx.x;
#pragma unroll
    for (int j = 0; j < 2; j++) {
        const int idx = tid + j * 256;
        const int r = idx >> 2, sg = (idx & 3) * 4;
        const size_t ao = (size_t)(m0 + r) * KH + kc2 + sg;
        const size_t bo = (size_t)(n0 + r) * KH + kc2 + sg;
        const uint32_t d = sbase + (r * GROW + sg) * 4;
        cp16(d + G_AH * 4, AH + ao);
        cp16(d + G_AL * 4, AL + ao);
        cp16(d + G_BH * 4, BH + bo);
        cp16(d + G_BL * 4, BL + bo);
    }
    CP_COMMIT();
}

template <int MODE>
__device__ __forceinline__ void gemm_tile_pk(
    const uint32_t* __restrict__ AH, const uint32_t* __restrict__ AL,
    const uint32_t* __restrict__ BH, const uint32_t* __restrict__ BL,
    const float* __restrict__ bias, float* __restrict__ C,
    int N, int KH, int m0, int n0, float premul)
{
    extern __shared__ uint32_t su[];
    const uint32_t sbase = smem_u32p(su);

    const int tid = threadIdx.x;
    const int lane = tid & 31;
    const int wid = tid >> 5;
    const int wm = (wid >> 2) * 64;
    const int wn = (wid & 3) * 32;
    const int lr = lane >> 2;
    const int lc = lane & 3;
    const int lt = lane >> 3;
    const int lrr = lane & 7;

    const uint32_t aBase = sbase +
        (((wm + (lt & 1) * 8 + lrr) * GROW + (lt >> 1) * 4) << 2);
    const uint32_t bBase = sbase +
        ((G_BH + (wn + (lt >> 1) * 8 + lrr) * GROW + (lt & 1) * 4) << 2);

    float acc[4][4][4];
#pragma unroll
    for (int i = 0; i < 4; i++)
#pragma unroll
        for (int j = 0; j < 4; j++)
#pragma unroll
            for (int k = 0; k < 4; k++) acc[i][j][k] = 0.0f;

    const int NC = KH / 16;
    int buf = 0;

    gemm_stage(sbase, AH, AL, BH, BL, KH, m0, n0, 0);

    for (int c = 0; c < NC; c++) {
        CP_WAIT0();
        __syncthreads();
        if (c + 1 < NC)
            gemm_stage(sbase + (buf ^ 1) * G_U32 * 4,
                       AH, AL, BH, BL, KH, m0, n0, (c + 1) * 16);

        const uint32_t bufo = (uint32_t)buf * G_U32 * 4;
#pragma unroll
        for (int ss = 0; ss < 2; ss++) {
            uint32_t bh[4][2], bl[4][2];
#pragma unroll
            for (int p = 0; p < 2; p++) {
                const uint32_t off = bufo + ((p * 16 * GROW + ss * 8) << 2);
                ldsm4(bh[2 * p][0], bh[2 * p][1], bh[2 * p + 1][0],
                      bh[2 * p + 1][1], bBase + off);
                ldsm4(bl[2 * p][0], bl[2 * p][1], bl[2 * p + 1][0],
                      bl[2 * p + 1][1], bBase + off + ((128 * GROW) << 2));
            }
#pragma unroll
            for (int mt = 0; mt < 4; mt++) {
                const uint32_t off = bufo + ((mt * 16 * GROW + ss * 8) << 2);
                uint32_t ah0, ah1, ah2, ah3, al0, al1, al2, al3;
                ldsm4(ah0, ah1, ah2, ah3, aBase + off);
                ldsm4(al0, al1, al2, al3, aBase + off + ((G_AL) << 2));
#pragma unroll
                for (int nt = 0; nt < 4; nt++) {
                    mma16816(acc[mt][nt], ah0, ah1, ah2, ah3, bh[nt][0], bh[nt][1]);
                    mma16816(acc[mt][nt], ah0, ah1, ah2, ah3, bl[nt][0], bl[nt][1]);
                    mma16816(acc[mt][nt], al0, al1, al2, al3, bh[nt][0], bh[nt][1]);
                }
            }
        }
        buf ^= 1;
    }

#pragma unroll
    for (int nt = 0; nt < 4; nt++) {
        const int n = n0 + wn + nt * 8 + lc * 2;
        const float2 bv = *(const float2*)(bias + n);
#pragma unroll
        for (int mt = 0; mt < 4; mt++) {
            const int m = m0 + wm + mt * 16 + lr;
            if (MODE == 0) {
                *(float2*)(C + (size_t)m * N + n) =
                    make_float2(acc[mt][nt][0] + bv.x, acc[mt][nt][1] + bv.y);
                *(float2*)(C + (size_t)(m + 8) * N + n) =
                    make_float2(acc[mt][nt][2] + bv.x, acc[mt][nt][3] + bv.y);
            } else if (MODE == 1) {
                *(float2*)(C + (size_t)m * N + n) =
                    make_float2(f2tf32((acc[mt][nt][0] + bv.x) * premul),
                                f2tf32((acc[mt][nt][1] + bv.y) * premul));
                *(float2*)(C + (size_t)(m + 8) * N + n) =
                    make_float2(f2tf32((acc[mt][nt][2] + bv.x) * premul),
                                f2tf32((acc[mt][nt][3] + bv.y) * premul));
            } else if (MODE == 2) {
                C[kaddr(m, n)]         = f2tf32(acc[mt][nt][0] + bv.x);
                C[kaddr(m, n + 1)]     = f2tf32(acc[mt][nt][1] + bv.y);
                C[kaddr(m + 8, n)]     = f2tf32(acc[mt][nt][2] + bv.x);
                C[kaddr(m + 8, n + 1)] = f2tf32(acc[mt][nt][3] + bv.y);
            } else {
                C[vaddr(m, n)]         = f2tf32(acc[mt][nt][0] + bv.x);
                C[vaddr(m, n + 1)]     = f2tf32(acc[mt][nt][1] + bv.y);
                C[vaddr(m + 8, n)]     = f2tf32(acc[mt][nt][2] + bv.x);
                C[vaddr(m + 8, n + 1)] = f2tf32(acc[mt][nt][3] + bv.y);
            }
        }
    }
}

__global__ __launch_bounds__(256, 2) void gemm_qkv(
    const float* __restrict__ bq, const float* __restrict__ bk,
    const float* __restrict__ bv,
    float* __restrict__ Q, float* __restrict__ K, float* __restrict__ V)
{
    const int col0 = blockIdx.x * 128;
    const int m0 = blockIdx.y * 128;
    if (col0 < D_MODEL) {
        gemm_tile_pk<1>(g_xh, g_xl, g_WqTh, g_WqTl, bq, Q, D_MODEL, KH2,
                        m0, col0, QSCALE);
    } else if (col0 < D_MODEL + KV_DIM) {
        gemm_tile_pk<2>(g_xh, g_xl, g_WkTh, g_WkTl, bk, K, KV_DIM, KH2,
                        m0, col0 - D_MODEL, 1.0f);
    } else {
        gemm_tile_pk<3>(g_xh, g_xl, g_WvTh, g_WvTl, bv, V, KV_DIM, KH2,
                        m0, col0 - D_MODEL - KV_DIM, 1.0f);
    }
}

__global__ __launch_bounds__(256, 2) void gemm_o(
    const float* __restrict__ bias, float* __restrict__ C)
{
    gemm_tile_pk<0>(g_Oh, g_Ol, g_WoTh, g_WoTl, bias, C, D_MODEL, KH2,
                    blockIdx.y * 128, blockIdx.x * 128, 1.0f);
}

// ---------------------------------------------------------------------------
// Causal GQA flash attention (tf32 mma.sync, R12/R14 numerics).
// - Q fragments loaded ONCE per job via LDG (no Q smem).
// - P never touches smem: S C-fragments -> PV A-fragments via quad shuffles.
// - K/V triple-buffered, ONE __syncthreads per iteration.
// - Fragment LDS.128 loads software-pipelined one step ahead (S and PV loops).
// - Single-barrier job grab via parity-indexed sjob.
// ---------------------------------------------------------------------------
#define KS_ST 80                        // 64 payload + 16 pad: LDS.128 clean
#define KS_BUF (64 * KS_ST)             // 5120 floats
#define OFF_VS (3 * KS_BUF)             // 15360
#define VS_BUF 4096                     // 64 t x 64 d floats (quad layout)
#define ATTN_SMEM ((OFF_VS + 3 * VS_BUF) * 4)   // 110592 B

// Transform one k8 C-fragment of S into a PV A-fragment (intra-quad shuffles).
#define XFORM(sa_j, A0, A1, A2, A3) do {                                      \
    const int _s0 = (lane & 28) | (lc >> 1);                                  \
    const float _t0 = __shfl_sync(0xffffffffu, (sa_j)[0], _s0);               \
    const float _t1 = __shfl_sync(0xffffffffu, (sa_j)[1], _s0);               \
    const float _u0 = __shfl_sync(0xffffffffu, (sa_j)[2], _s0);               \
    const float _u1 = __shfl_sync(0xffffffffu, (sa_j)[3], _s0);               \
    const float _t2 = __shfl_sync(0xffffffffu, (sa_j)[0], _s0 + 2);           \
    const float _t3 = __shfl_sync(0xffffffffu, (sa_j)[1], _s0 + 2);           \
    const float _u2 = __shfl_sync(0xffffffffu, (sa_j)[2], _s0 + 2);           \
    const float _u3 = __shfl_sync(0xffffffffu, (sa_j)[3], _s0 + 2);           \
    A0 = (lc & 1) ? _t1 : _t0;                                                \
    A1 = (lc & 1) ? _u1 : _u0;                                                \
    A2 = (lc & 1) ? _t3 : _t2;                                                \
    A3 = (lc & 1) ? _u3 : _u2;                                                \
} while (0)

__global__ __launch_bounds__(256, 2) void attn_mma()
{
    extern __shared__ float sm[];
    const uint32_t sbase = smem_u32p(sm);
    __shared__ int sjob[2];

    const int tid = threadIdx.x;
    const int lane = tid & 31;
    const int w = tid >> 5;
    const int lr = lane >> 2;
    const int lc = lane & 3;
    const int r0 = w * 16 + lr;

    int jc = 0;
    for (;;) {
        if (tid == 0) sjob[jc & 1] = atomicAdd(&g_jobctr, 1);
        __syncthreads();   // single barrier per job grab (parity slot)
        const int job = sjob[jc & 1];
        jc++;
        if (job >= N_JOBS) break;

        const int qt = 15 - (job >> 5);
        const int h = job & 15;
        const int b = (job >> 4) & 1;
        const int g = h >> 2;
        const int tb = b * TSEQ;
        const int nkt = 2 * qt + 2;
        const float* kbase = g_Kp + (size_t)(b * 4 + g) * PLANE;
        const float* vbase = g_Vp + (size_t)(b * 4 + g) * PLANE;

        auto stage_kv = [&](int kt) {
            const int bf = kt % 3;
            const int krow = tid >> 2, kseg = (tid & 3) * 16;
            const float* kr = kbase + (size_t)(kt * 64 + krow) * 64 + kseg;
            const uint32_t kd = sbase + (bf * KS_BUF + krow * KS_ST + kseg) * 4;
#pragma unroll
            for (int i = 0; i < 4; i++) cp16(kd + i * 16, kr + i * 4);
            const float* vr = vbase + (size_t)kt * 4096 + tid * 16;
            const uint32_t vd = sbase + (OFF_VS + bf * VS_BUF + tid * 16) * 4;
#pragma unroll
            for (int i = 0; i < 4; i++) cp16(vd + i * 16, vr + i * 4);
            CP_COMMIT();
        };

        stage_kv(0);
        stage_kv(1);

        // Q fragments via direct LDG (pre-scaled + tf32-rounded by gemm_qkv).
        float qf[8][4];
        {
            const float* q0 = g_Q + (size_t)(tb + qt * 128 + r0) * D_MODEL
                              + h * HEAD_DIM;
            const float* q1 = q0 + 8 * D_MODEL;
#pragma unroll
            for (int kb8 = 0; kb8 < 8; kb8++) {
                qf[kb8][0] = q0[kb8 * 8 + lc];
                qf[kb8][1] = q1[kb8 * 8 + lc];
                qf[kb8][2] = q0[kb8 * 8 + lc + 4];
                qf[kb8][3] = q1[kb8 * 8 + lc + 4];
            }
        }

        float oacc[8][4];
#pragma unroll
        for (int nt = 0; nt < 8; nt++)
#pragma unroll
            for (int j = 0; j < 4; j++) oacc[nt][j] = 0.0f;
        float m0 = -1e30f, m1 = -1e30f, l0 = 0.0f, l1 = 0.0f;

        const int qi0 = qt * 128 + r0;
        const int qi1 = qi0 + 8;

        for (int kt = 0; kt < nkt; kt++) {
            if (kt + 1 < nkt) { CP_WAIT1(); } else { CP_WAIT0(); }
            __syncthreads();   // the ONLY per-iteration barrier
            const int bf = kt % 3;
            const float* Ks = sm + bf * KS_BUF;
            const float* Vs = sm + OFF_VS + bf * VS_BUF;

            // S = Q @ K^T : flat loop, LDS.128 prefetched one step ahead.
            float sa[8][4];
#pragma unroll
            for (int nt = 0; nt < 8; nt++)
#pragma unroll
                for (int j = 0; j < 4; j++) sa[nt][j] = 0.0f;
            {
                float4 kk = *(const float4*)(Ks + lr * KS_ST + lc * 4);
#pragma unroll
                for (int idx = 0; idx < 32; idx++) {
                    const int kb16 = idx >> 3, nt = idx & 7;
                    float4 nxt;
                    if (idx < 31) {
                        const int i2 = idx + 1;
                        nxt = *(const float4*)(Ks +
                            ((i2 & 7) * 8 + lr) * KS_ST + (i2 >> 3) * 16 + lc * 4);
                    }
                    mma1688(sa[nt], qf[2 * kb16][0], qf[2 * kb16][1],
                            qf[2 * kb16][2], qf[2 * kb16][3], kk.x, kk.y);
                    mma1688(sa[nt], qf[2 * kb16 + 1][0], qf[2 * kb16 + 1][1],
                            qf[2 * kb16 + 1][2], qf[2 * kb16 + 1][3], kk.z, kk.w);
                    if (idx < 31) kk = nxt;
                }
            }

            if (kt >= 2 * qt) {
#pragma unroll
                for (int nt = 0; nt < 8; nt++) {
                    const int kj = kt * 64 + nt * 8 + 2 * lc;
                    if (kj > qi0)     sa[nt][0] = -1e30f;
                    if (kj + 1 > qi0) sa[nt][1] = -1e30f;
                    if (kj > qi1)     sa[nt][2] = -1e30f;
                    if (kj + 1 > qi1) sa[nt][3] = -1e30f;
                }
            }

            // Online softmax (log2 domain).
            float mx0 = sa[0][0], mx1 = sa[0][2];
#pragma unroll
            for (int nt = 0; nt < 8; nt++) {
                mx0 = fmaxf(mx0, fmaxf(sa[nt][0], sa[nt][1]));
                mx1 = fmaxf(mx1, fmaxf(sa[nt][2], sa[nt][3]));
            }
            mx0 = fmaxf(mx0, __shfl_xor_sync(0xffffffffu, mx0, 1));
            mx0 = fmaxf(mx0, __shfl_xor_sync(0xffffffffu, mx0, 2));
            mx1 = fmaxf(mx1, __shfl_xor_sync(0xffffffffu, mx1, 1));
            mx1 = fmaxf(mx1, __shfl_xor_sync(0xffffffffu, mx1, 2));
            const float nm0 = fmaxf(m0, mx0), nm1 = fmaxf(m1, mx1);
            const float cf0 = exp2f(m0 - nm0), cf1 = exp2f(m1 - nm1);
            m0 = nm0; m1 = nm1;
            float rs0 = 0.0f, rs1 = 0.0f;
#pragma unroll
            for (int nt = 0; nt < 8; nt++) {
                float p0 = exp2f(sa[nt][0] - nm0);
                float p1 = exp2f(sa[nt][1] - nm0);
                float p2 = exp2f(sa[nt][2] - nm1);
                float p3 = exp2f(sa[nt][3] - nm1);
                rs0 += p0 + p1; rs1 += p2 + p3;
                sa[nt][0] = f2tf32(p0); sa[nt][1] = f2tf32(p1);
                sa[nt][2] = f2tf32(p2); sa[nt][3] = f2tf32(p3);
            }
            rs0 += __shfl_xor_sync(0xffffffffu, rs0, 1);
            rs0 += __shfl_xor_sync(0xffffffffu, rs0, 2);
            rs1 += __shfl_xor_sync(0xffffffffu, rs1, 1);
            rs1 += __shfl_xor_sync(0xffffffffu, rs1, 2);
            l0 = l0 * cf0 + rs0;
            l1 = l1 * cf1 + rs1;
#pragma unroll
            for (int nt = 0; nt < 8; nt++) {
                oacc[nt][0] *= cf0; oacc[nt][1] *= cf0;
                oacc[nt][2] *= cf1; oacc[nt][3] *= cf1;
            }

            // O += P @ V : P fragments via quad shuffles; V LDS.128 prefetched
            // one step ahead (first load issues before the XFORM chain).
            {
                float4 vv = *(const float4*)(Vs + lr * 16 + lc * 4);
#pragma unroll
                for (int kb16 = 0; kb16 < 4; kb16++) {
                    float a0, a1, a2, a3, b0, b1, b2, b3;
                    XFORM(sa[2 * kb16],     a0, a1, a2, a3);
                    XFORM(sa[2 * kb16 + 1], b0, b1, b2, b3);
#pragma unroll
                    for (int nt = 0; nt < 8; nt++) {
                        const int idx = kb16 * 8 + nt;
                        float4 nxt;
                        if (idx < 31) {
                            const int i2 = idx + 1;
                            nxt = *(const float4*)(Vs +
                                (i2 >> 3) * 1024 + ((i2 & 7) * 8 + lr) * 16 + lc * 4);
                        }
                        mma1688(oacc[nt], a0, a1, a2, a3, vv.x, vv.y);
                        mma1688(oacc[nt], b0, b1, b2, b3, vv.z, vv.w);
                        if (idx < 31) vv = nxt;
                    }
                }
            }
            // No barrier: triple-buffered K/V, reuse distance 2 iterations.
            if (kt + 2 < nkt) stage_kv(kt + 2);
        }

        // Normalize; write packed bf16x2 hi/lo (feeds gemm_o).
        const float inv0 = 1.0f / l0, inv1 = 1.0f / l1;
        const size_t row0 = (size_t)(tb + qt * 128 + r0);
        const int colp = h * 32 + lc;
#pragma unroll
        for (int nt = 0; nt < 8; nt++) {
            float v0 = oacc[nt][0] * inv0, v1 = oacc[nt][1] * inv0;
            float v2 = oacc[nt][2] * inv1, v3 = oacc[nt][3] * inv1;
            __nv_bfloat16 h0 = __float2bfloat16_rn(v0);
            __nv_bfloat16 h1 = __float2bfloat16_rn(v1);
            __nv_bfloat16 h2 = __float2bfloat16_rn(v2);
            __nv_bfloat16 h3 = __float2bfloat16_rn(v3);
            const size_t o0 = row0 * KH2 + colp + nt * 4;
            const size_t o1 = (row0 + 8) * KH2 + colp + nt * 4;
            g_Oh[o0] = packbf(h0, h1);
            g_Ol[o0] = packbf(__float2bfloat16_rn(v0 - __bfloat162float(h0)),
                              __float2bfloat16_rn(v1 - __bfloat162float(h1)));
            g_Oh[o1] = packbf(h2, h3);
            g_Ol[o1] = packbf(__float2bfloat16_rn(v2 - __bfloat162float(h2)),
                              __float2bfloat16_rn(v3 - __bfloat162float(h3)));
        }
    }
}

// ---------------------------------------------------------------------------
extern "C" void kernel_launch(void* const* d_in, const int* in_sizes, int n_in,
                              void* d_out, int out_size)
{
    const float* x  = (const float*)d_in[0];
    const float* Wq = (const float*)d_in[1];
    const float* bq = (const float*)d_in[2];
    const float* Wk = (const float*)d_in[3];
    const float* bk = (const float*)d_in[4];
    const float* Wv = (const float*)d_in[5];
    const float* bv = (const float*)d_in[6];
    const float* Wo = (const float*)d_in[7];
    const float* bo = (const float*)d_in[8];
    float* out = (float*)d_out;

    float *Qp, *Kp, *Vp;
    uint32_t *xh, *xl;
    cudaGetSymbolAddress((void**)&Qp, g_Q);
    cudaGetSymbolAddress((void**)&Kp, g_Kp);
    cudaGetSymbolAddress((void**)&Vp, g_Vp);
    cudaGetSymbolAddress((void**)&xh, g_xh);
    cudaGetSymbolAddress((void**)&xl, g_xl);

    cudaFuncSetAttribute(gemm_qkv, cudaFuncAttributeMaxDynamicSharedMemorySize, GEMM_SMEM);
    cudaFuncSetAttribute(gemm_o,   cudaFuncAttributeMaxDynamicSharedMemorySize, GEMM_SMEM);
    cudaFuncSetAttribute(attn_mma, cudaFuncAttributeMaxDynamicSharedMemorySize, ATTN_SMEM);

    // One-shot conversions (+ job counter reset inside conv_pack).
    conv_pack<<<(BT * D_MODEL / 4 + 255) / 256, 256>>>(x, xh, xl, BT * D_MODEL / 4);
    conv_wT_all<<<dim3(D_MODEL / 32, D_MODEL / 32, 4), dim3(32, 8)>>>(Wq, Wk, Wv, Wo);

    // Fused QKV projection (Q tf32+scaled; K tf32 d-quads; V tf32 t-quads).
    gemm_qkv<<<dim3((D_MODEL + 2 * KV_DIM) / 128, BT / 128), 256, GEMM_SMEM>>>(
        bq, bk, bv, Qp, Kp, Vp);

    // Causal GQA attention (persistent CTAs = exact 2-per-SM residency).
    attn_mma<<<296, 256, ATTN_SMEM>>>();

    // Output projection.
    gemm_o<<<dim3(D_MODEL / 128, BT / 128), 256, GEMM_SMEM>>>(bo, out);
}